// round 14
// baseline (speedup 1.0000x reference)
#include <cuda_runtime.h>
#include <cuda_bf16.h>
#include <math.h>
#include <stdint.h>

#define Bsz 32
#define Tlen 128
#define Hdim 1024
#define Vsz 32000
#define NB 128
#define NT 512

// ---------------- recurrence smem layout (byte offsets) ----------------
#define RTS1  264
#define RTS1B 528
#define RTS2  136
#define RTS2B 272
#define WSLOT 34816
#define SW_H(b) ((b) * WSLOT)
#define SW_L(b) ((b) * WSLOT + 17408)
#define SX_H(b) (139264 + (b) * 33792)
#define SX_L(b) (139264 + (b) * 33792 + 16896)
// P overlays X buffer region (last X read is buf 1; P written after, sync-separated)
#define SP_OFF  139264
#define R_SMEM_BYTES 206848

// ---------------- device scratch ----------------
__device__ float g_XT[Tlen * Bsz * Hdim];        // [t][b][k]
__device__ float g_h1a[Bsz * Hdim], g_h1b[Bsz * Hdim];
__device__ float g_h2a[Bsz * Hdim], g_h2b[Bsz * Hdim];
__device__ float g_c1[Bsz * Hdim],  g_c2[Bsz * Hdim];
__device__ float g_xA1[Bsz * Hdim], g_xB1[Bsz * Hdim];
__device__ float g_hA1[Bsz * Hdim], g_hB1[Bsz * Hdim];
__device__ float g_xA2[Bsz * Hdim], g_xB2[Bsz * Hdim];
__device__ float g_hA2[Bsz * Hdim], g_hB2[Bsz * Hdim];
__device__ unsigned g_bar_count;
__device__ volatile unsigned g_bar_sense;

// bf16 hi/lo weight arena
#define WOFF_M1   0
#define WOFF_M2   5242880
#define WOFF_G1IH 10485760
#define WOFF_G1HH 14680064
#define WOFF_G2IH 18874368
#define WOFF_G2HH 23068672
#define WTOTAL    27262976
__device__ __nv_bfloat16 g_wh[WTOTAL];
__device__ __nv_bfloat16 g_wl[WTOTAL];

// bf16 hi/lo splits for logits GEMM
__device__ __nv_bfloat16 g_embh[(size_t)Vsz * Hdim];
__device__ __nv_bfloat16 g_embl[(size_t)Vsz * Hdim];
__device__ __nv_bfloat16 g_hidh[(size_t)Bsz * Tlen * Hdim];
__device__ __nv_bfloat16 g_hidl[(size_t)Bsz * Tlen * Hdim];

// ---------------- grid-wide barrier (sense reversing, replay-safe) ----------------
__device__ __forceinline__ void grid_barrier(unsigned& sense) {
    __threadfence();
    __syncthreads();
    if (threadIdx.x == 0) {
        unsigned s = sense ^ 1u;
        if (atomicAdd(&g_bar_count, 1u) == NB - 1u) {
            g_bar_count = 0u;
            __threadfence();
            g_bar_sense = s;
        } else {
            while (g_bar_sense != s) __nanosleep(32);
        }
    }
    __syncthreads();
    __threadfence();
    sense ^= 1u;
}

// ---------------- helpers ----------------
__device__ __forceinline__ void mma_bf16(float d[4], const uint32_t a[4],
                                         const uint32_t b[2]) {
    asm volatile(
        "mma.sync.aligned.m16n8k16.row.col.f32.bf16.bf16.f32 "
        "{%0,%1,%2,%3},{%4,%5,%6,%7},{%8,%9},{%0,%1,%2,%3};"
        : "+f"(d[0]), "+f"(d[1]), "+f"(d[2]), "+f"(d[3])
        : "r"(a[0]), "r"(a[1]), "r"(a[2]), "r"(a[3]), "r"(b[0]), "r"(b[1]));
}

__device__ __forceinline__ void cp16(uint32_t saddr, const void* g) {
    asm volatile("cp.async.cg.shared.global [%0], [%1], 16;" :: "r"(saddr), "l"(g));
}
#define CP_COMMIT() asm volatile("cp.async.commit_group;" ::: "memory")
template <int N>
__device__ __forceinline__ void cp_wait() {
    asm volatile("cp.async.wait_group %0;" :: "n"(N) : "memory");
}

__device__ __forceinline__ uint32_t pack_bf2(float a, float b) {
    __nv_bfloat162 t(__float2bfloat16_rn(a), __float2bfloat16_rn(b));
    return *(uint32_t*)&t;
}

// ---- activation staging ----
template <int KCH, int RTSBx>
__device__ __forceinline__ void x_prefetch(const float* __restrict__ src, int kb,
                                           float4* xr) {
    int tid = threadIdx.x;
    const int CELLS = Bsz * KCH / 4;
#pragma unroll
    for (int i = 0; i < CELLS / NT; i++) {
        int idx = tid + i * NT;
        int b = idx / (KCH / 4), q = idx % (KCH / 4);
        xr[i] = *(const float4*)&src[(size_t)b * Hdim + kb + q * 4];
    }
}
template <int KCH, int RTSBx>
__device__ __forceinline__ void x_store(char* sm, int buf, const float4* xr) {
    int tid = threadIdx.x;
    char* XH = sm + SX_H(buf);
    char* XL = sm + SX_L(buf);
    const int CELLS = Bsz * KCH / 4;
#pragma unroll
    for (int i = 0; i < CELLS / NT; i++) {
        int idx = tid + i * NT;
        int b = idx / (KCH / 4), q = idx % (KCH / 4);
        float4 v = xr[i];
        float hx = __bfloat162float(__float2bfloat16_rn(v.x));
        float hy = __bfloat162float(__float2bfloat16_rn(v.y));
        float hz = __bfloat162float(__float2bfloat16_rn(v.z));
        float hw = __bfloat162float(__float2bfloat16_rn(v.w));
        uint2 uh = make_uint2(pack_bf2(v.x, v.y), pack_bf2(v.z, v.w));
        uint2 ul = make_uint2(pack_bf2(v.x - hx, v.y - hy), pack_bf2(v.z - hz, v.w - hw));
        int off = b * RTSBx + q * 8;
        *(uint2*)(XH + off) = uh;
        *(uint2*)(XL + off) = ul;
    }
}

// ---- m16 fragment mma ----
template <int RTSx, int KSTEPS>
__device__ __forceinline__ void frag16(char* sm, int wbuf, int xbuf, int rowBase,
                                       int kw, int gr, int tig, float acc[4][4]) {
    const __nv_bfloat16* WhS = (const __nv_bfloat16*)(sm + SW_H(wbuf));
    const __nv_bfloat16* WlS = (const __nv_bfloat16*)(sm + SW_L(wbuf));
    const __nv_bfloat16* XhS = (const __nv_bfloat16*)(sm + SX_H(xbuf));
    const __nv_bfloat16* XlS = (const __nv_bfloat16*)(sm + SX_L(xbuf));
#pragma unroll
    for (int ks = 0; ks < KSTEPS; ks++) {
        int k0 = kw + ks * 16 + 2 * tig;
        uint32_t ah[4], al[4], bh[4][2], bl[4][2];
        int base = (rowBase + gr) * RTSx + k0;
        ah[0] = *(const uint32_t*)&WhS[base];
        ah[1] = *(const uint32_t*)&WhS[base + 8 * RTSx];
        ah[2] = *(const uint32_t*)&WhS[base + 8];
        ah[3] = *(const uint32_t*)&WhS[base + 8 * RTSx + 8];
        al[0] = *(const uint32_t*)&WlS[base];
        al[1] = *(const uint32_t*)&WlS[base + 8 * RTSx];
        al[2] = *(const uint32_t*)&WlS[base + 8];
        al[3] = *(const uint32_t*)&WlS[base + 8 * RTSx + 8];
#pragma unroll
        for (int nf = 0; nf < 4; nf++) {
            int xb = (nf * 8 + gr) * RTSx + k0;
            bh[nf][0] = *(const uint32_t*)&XhS[xb];
            bh[nf][1] = *(const uint32_t*)&XhS[xb + 8];
            bl[nf][0] = *(const uint32_t*)&XlS[xb];
            bl[nf][1] = *(const uint32_t*)&XlS[xb + 8];
        }
#pragma unroll
        for (int nf = 0; nf < 4; nf++) {
            mma_bf16(acc[nf], ah, bh[nf]);
            mma_bf16(acc[nf], al, bh[nf]);
            mma_bf16(acc[nf], ah, bl[nf]);
        }
    }
}

// ---- W prefetch (issued BEFORE the barrier preceding the stage) ----
__device__ __forceinline__ void mog_prefW(const __nv_bfloat16* __restrict__ Wh,
                                          const __nv_bfloat16* __restrict__ Wl,
                                          int lb, uint32_t smb) {
    int tid = threadIdx.x;
    int wr = tid >> 5, wu = tid & 31;
    size_t wgbase = (size_t)(lb * 16 + wr) * Hdim + wu * 8;
    uint32_t wsoff = wr * RTS1B + wu * 16;
#pragma unroll
    for (int c = 0; c < 4; c++) {
        cp16(smb + SW_H(c) + wsoff, Wh + wgbase + c * 256);
        cp16(smb + SW_L(c) + wsoff, Wl + wgbase + c * 256);
        CP_COMMIT();
    }
}
__device__ __forceinline__ void gate_prefW(const __nv_bfloat16* __restrict__ WihH,
                                           const __nv_bfloat16* __restrict__ WihL,
                                           int lb, uint32_t smb) {
    int tid = threadIdx.x;
    int j0u = lb * 16;
#pragma unroll
    for (int cn = 0; cn < 3; cn++) {        // chunks 0..2 (all within Wih)
        int cbase = cn * 128;
#pragma unroll
        for (int i = 0; i < 2; i++) {
            int idx = tid + i * NT;
            int r = idx >> 4, u = idx & 15;
            int grow = (r >> 4) * Hdim + j0u + (r & 15);
            size_t go = (size_t)grow * Hdim + cbase + u * 8;
            cp16(smb + SW_H(cn) + r * RTS2B + u * 16, WihH + go);
            cp16(smb + SW_L(cn) + r * RTS2B + u * 16, WihL + go);
        }
        CP_COMMIT();
    }
}

// ---------------- mogrify stage (W chunks 0..3 pre-issued as 4 groups) --------------
__device__ void mog_stage(const float* __restrict__ bias,
                          const float* __restrict__ src,
                          const float* __restrict__ mult,
                          float* __restrict__ dstNew,
                          int lb, char* sm)
{
    int tid = threadIdx.x, lane = tid & 31, w = tid >> 5;
    int gr = lane >> 2, tig = lane & 3;
    int j0 = lb * 16;
    float* P = (float*)(sm + SP_OFF);

    float acc[4][4];
#pragma unroll
    for (int nf = 0; nf < 4; nf++)
#pragma unroll
        for (int q = 0; q < 4; q++) acc[nf][q] = 0.f;

    // X chunk 0
    {
        float4 xr[4];
        x_prefetch<256, RTS1B>(src, 0, xr);
        x_store<256, RTS1B>(sm, 0, xr);
    }

#pragma unroll
    for (int c = 0; c < 4; c++) {
        float4 xr[4];
        if (c < 3) x_prefetch<256, RTS1B>(src, (c + 1) * 256, xr);
        if (c == 0) cp_wait<3>();
        else if (c == 1) cp_wait<2>();
        else if (c == 2) cp_wait<1>();
        else cp_wait<0>();
        __syncthreads();
        frag16<RTS1, 1>(sm, c, c & 1, 0, w * 16, gr, tig, acc);
        if (c < 3) x_store<256, RTS1B>(sm, (c + 1) & 1, xr);
        __syncthreads();
    }

#pragma unroll
    for (int nf = 0; nf < 4; nf++) {
        int cc = nf * 8 + 2 * tig;
        *(float2*)&P[w * 512 + gr * 32 + cc]       = make_float2(acc[nf][0], acc[nf][1]);
        *(float2*)&P[w * 512 + (gr + 8) * 32 + cc] = make_float2(acc[nf][2], acc[nf][3]);
    }
    __syncthreads();

    {
        float s = 0.f;
#pragma unroll
        for (int ww = 0; ww < 16; ww++) s += P[ww * 512 + tid];
        int row = tid >> 5, b = tid & 31;
        int j = j0 + row;
        s += bias[j];
        size_t o = (size_t)b * Hdim + j;
        dstNew[o] = mult[o] * (2.f / (1.f + __expf(-s)));
    }
    __syncthreads();    // P consumed before caller's prefetch may reuse X region
}

// ---------------- gate stage (W chunks 0..2 pre-issued as 3 groups) ----------------
__device__ void gate_stage(const __nv_bfloat16* __restrict__ WihH,
                           const __nv_bfloat16* __restrict__ WihL,
                           const __nv_bfloat16* __restrict__ WhhH,
                           const __nv_bfloat16* __restrict__ WhhL,
                           const float* __restrict__ bih, const float* __restrict__ bhh,
                           const float* __restrict__ xsrc, const float* __restrict__ hsrc,
                           float* __restrict__ cSt, float* __restrict__ hDst,
                           float* __restrict__ hidOut, int t,
                           int lb, char* sm, uint32_t smb)
{
    int tid = threadIdx.x, lane = tid & 31, w = tid >> 5;
    int gr = lane >> 2, tig = lane & 3;
    int mg = w >> 2, kg = w & 3;
    int j0u = lb * 16;
    float* P = (float*)(sm + SP_OFF);

    float acc[4][4];
#pragma unroll
    for (int nf = 0; nf < 4; nf++)
#pragma unroll
        for (int q = 0; q < 4; q++) acc[nf][q] = 0.f;

    auto stageW = [&](int buf, int cn) {
        const __nv_bfloat16* WmH = (cn < 8) ? WihH : WhhH;
        const __nv_bfloat16* WmL = (cn < 8) ? WihL : WhhL;
        int cbase = (cn & 7) * 128;
#pragma unroll
        for (int i = 0; i < 2; i++) {
            int idx = tid + i * NT;
            int r = idx >> 4, u = idx & 15;
            int grow = (r >> 4) * Hdim + j0u + (r & 15);
            size_t go = (size_t)grow * Hdim + cbase + u * 8;
            cp16(smb + SW_H(buf) + r * RTS2B + u * 16, WmH + go);
            cp16(smb + SW_L(buf) + r * RTS2B + u * 16, WmL + go);
        }
        CP_COMMIT();
    };

    // X chunk 0
    {
        float4 xr[2];
        x_prefetch<128, RTS2B>(xsrc, 0, xr);
        x_store<128, RTS2B>(sm, 0, xr);
    }

#pragma unroll
    for (int c = 0; c < 16; c++) {
        if (c + 3 < 16) stageW((c + 3) & 3, c + 3);
        float4 xr[2];
        if (c < 15) {
            int cn = c + 1;
            const float* S = (cn < 8) ? xsrc : hsrc;
            x_prefetch<128, RTS2B>(S, (cn & 7) * 128, xr);
        }
        if (c <= 12) cp_wait<3>();
        else if (c == 13) cp_wait<2>();
        else if (c == 14) cp_wait<1>();
        else cp_wait<0>();
        __syncthreads();
        frag16<RTS2, 2>(sm, c & 3, c & 1, mg * 16, kg * 32, gr, tig, acc);
        if (c < 15) x_store<128, RTS2B>(sm, (c + 1) & 1, xr);
        __syncthreads();
    }

#pragma unroll
    for (int nf = 0; nf < 4; nf++) {
        int cc = nf * 8 + 2 * tig;
        *(float2*)&P[kg * 2048 + (mg * 16 + gr) * 32 + cc] =
            make_float2(acc[nf][0], acc[nf][1]);
        *(float2*)&P[kg * 2048 + (mg * 16 + gr + 8) * 32 + cc] =
            make_float2(acc[nf][2], acc[nf][3]);
    }
    __syncthreads();

    {
        int u = tid >> 5, b = tid & 31;
        int j = j0u + u;
        float s[4];
#pragma unroll
        for (int g = 0; g < 4; g++) {
            int row = g * 16 + u;
            float v = 0.f;
#pragma unroll
            for (int k = 0; k < 4; k++) v += P[k * 2048 + row * 32 + b];
            s[g] = v;
        }
        float gi = s[0] + bih[j]            + bhh[j];
        float gf = s[1] + bih[Hdim + j]     + bhh[Hdim + j];
        float gg = s[2] + bih[2 * Hdim + j] + bhh[2 * Hdim + j];
        float go = s[3] + bih[3 * Hdim + j] + bhh[3 * Hdim + j];

        float si = 1.f / (1.f + __expf(-gi));
        float sf = 1.f / (1.f + __expf(-gf));
        float tg = tanhf(gg);
        float so = 1.f / (1.f + __expf(-go));

        size_t g = (size_t)b * Hdim + j;
        float cc = sf * cSt[g] + si * tg;
        float h = so * tanhf(cc);
        cSt[g] = cc;
        hDst[g] = h;
        if (hidOut) hidOut[(size_t)b * Tlen * Hdim + (size_t)t * Hdim + j] = h;
    }
    __syncthreads();    // P consumed before caller's prefetch may reuse X region
}

// ---------------- persistent recurrence kernel ----------------
__global__ __launch_bounds__(NT, 1) void mog_lstm_kernel(
    const int* __restrict__ seq, const float* __restrict__ emb,
    const float* __restrict__ m1b, const float* __restrict__ b1ih,
    const float* __restrict__ b1hh, const float* __restrict__ m2b,
    const float* __restrict__ b2ih, const float* __restrict__ b2hh,
    float* __restrict__ hidp)
{
    extern __shared__ char sm[];
    uint32_t smb;
    asm("{ .reg .u64 t; cvta.to.shared.u64 t, %1; cvt.u32.u64 %0, t; }"
        : "=r"(smb) : "l"(sm));
    int tid = threadIdx.x;
    int bid = blockIdx.x;
    int grp = bid >> 6;
    int lb  = bid & 63;
    unsigned sense = 0;
    const size_t MW = (size_t)Hdim * Hdim;

    for (int g = bid * NT + tid; g < Bsz * Hdim; g += NB * NT) {
        g_h1a[g] = 0.f; g_h1b[g] = 0.f; g_h2a[g] = 0.f; g_h2b[g] = 0.f;
        g_c1[g] = 0.f;  g_c2[g] = 0.f;
    }
    {
        int t = bid;
        for (int idx = tid; idx < Bsz * Hdim; idx += NT) {
            int b = idx >> 10, k = idx & 1023;
            int id = seq[b * Tlen + t];
            g_XT[((size_t)t * Bsz + b) * Hdim + k] = emb[(size_t)id * Hdim + k];
        }
    }
    // prefetch W for (phase 0, slot 0): only group A is active there
    if (grp == 0) mog_prefW(g_wh + WOFF_M1, g_wl + WOFF_M1, lb, smb);
    grid_barrier(sense);

    // prefetch selector for (phase np, slot ns) of THIS block's group
    auto prefetch_for = [&](int np, int ns) {
        if (grp == 0) {
            if (np >= Tlen) return;
            if (ns < 5) mog_prefW(g_wh + WOFF_M1 + (size_t)ns * MW,
                                  g_wl + WOFF_M1 + (size_t)ns * MW, lb, smb);
            else gate_prefW(g_wh + WOFF_G1IH, g_wl + WOFF_G1IH, lb, smb);
        } else {
            if (np < 1 || np > Tlen) return;
            if (ns < 5) mog_prefW(g_wh + WOFF_M2 + (size_t)ns * MW,
                                  g_wl + WOFF_M2 + (size_t)ns * MW, lb, smb);
            else gate_prefW(g_wh + WOFF_G2IH, g_wl + WOFF_G2IH, lb, smb);
        }
    };

    for (int p = 0; p <= Tlen; p++) {
        bool Aact = (grp == 0) && (p < Tlen);
        bool Bact = (grp == 1) && (p >= 1);
        int t2 = p - 1;

        const float* A_x = g_XT + (size_t)p * Bsz * Hdim;
        float* A_hs = (p & 1) ? g_h1b : g_h1a;
        float* A_hd = (p & 1) ? g_h1a : g_h1b;
        const float* B_x = (t2 & 1) ? g_h1a : g_h1b;
        float* B_hs = (t2 & 1) ? g_h2b : g_h2a;
        float* B_hd = (t2 & 1) ? g_h2a : g_h2b;

        const float* AsS[5] = { A_hs, g_xA1, g_hA1, g_xB1, g_hB1 };
        const float* AsM[5] = { A_x,  A_hs,  g_xA1, g_hA1, g_xB1 };
        float*       AsD[5] = { g_xA1, g_hA1, g_xB1, g_hB1, g_xA1 };
        const float* BsS[5] = { B_hs, g_xA2, g_hA2, g_xB2, g_hB2 };
        const float* BsM[5] = { B_x,  B_hs,  g_xA2, g_hA2, g_xB2 };
        float*       BsD[5] = { g_xA2, g_hA2, g_xB2, g_hB2, g_xA2 };

        for (int s = 0; s < 6; s++) {
            if (s < 5) {
                if (Aact)
                    mog_stage(m1b + s * Hdim, AsS[s], AsM[s], AsD[s], lb, sm);
                else if (Bact)
                    mog_stage(m2b + s * Hdim, BsS[s], BsM[s], BsD[s], lb, sm);
            } else {
                if (Aact)
                    gate_stage(g_wh + WOFF_G1IH, g_wl + WOFF_G1IH,
                               g_wh + WOFF_G1HH, g_wl + WOFF_G1HH,
                               b1ih, b1hh, g_xA1, g_hB1, g_c1, A_hd,
                               nullptr, p, lb, sm, smb);
                else if (Bact)
                    gate_stage(g_wh + WOFF_G2IH, g_wl + WOFF_G2IH,
                               g_wh + WOFF_G2HH, g_wl + WOFF_G2HH,
                               b2ih, b2hh, g_xA2, g_hB2, g_c2, B_hd,
                               hidp, t2, lb, sm, smb);
            }
            // prefetch next slot's W (overlaps with barrier wait)
            int np = p, ns = s + 1;
            if (ns == 6) { ns = 0; np++; }
            if (np <= Tlen) prefetch_for(np, ns);
            grid_barrier(sense);
        }
    }
    grid_barrier(sense);   // total = 1 + 129*6 + 1 = 776 (even: sense restored)
}

// ================= bf16 hi/lo split =================
__global__ void split_bf16_kernel(const float* __restrict__ src,
                                  __nv_bfloat16* __restrict__ hi,
                                  __nv_bfloat16* __restrict__ lo, size_t n4)
{
    for (size_t i = blockIdx.x * blockDim.x + threadIdx.x; i < n4;
         i += (size_t)gridDim.x * blockDim.x) {
        float4 v = *(const float4*)(src + i * 4);
        __nv_bfloat16 h0 = __float2bfloat16_rn(v.x);
        __nv_bfloat16 h1 = __float2bfloat16_rn(v.y);
        __nv_bfloat16 h2 = __float2bfloat16_rn(v.z);
        __nv_bfloat16 h3 = __float2bfloat16_rn(v.w);
        __nv_bfloat16 l0 = __float2bfloat16_rn(v.x - __bfloat162float(h0));
        __nv_bfloat16 l1 = __float2bfloat16_rn(v.y - __bfloat162float(h1));
        __nv_bfloat16 l2 = __float2bfloat16_rn(v.z - __bfloat162float(h2));
        __nv_bfloat16 l3 = __float2bfloat16_rn(v.w - __bfloat162float(h3));
        __nv_bfloat162* hp = (__nv_bfloat162*)(hi + i * 4);
        __nv_bfloat162* lp = (__nv_bfloat162*)(lo + i * 4);
        hp[0] = __nv_bfloat162(h0, h1);
        hp[1] = __nv_bfloat162(h2, h3);
        lp[0] = __nv_bfloat162(l0, l1);
        lp[1] = __nv_bfloat162(l2, l3);
    }
}

// ================= bf16x3 legacy-mma logits GEMM (unchanged, passing) =================
#define GTS 72
#define G_SMEM_BYTES (4 * 128 * GTS * 2)

__global__ __launch_bounds__(256, 2) void gemm_bf16x3_bias(
    const float* __restrict__ bias, float* __restrict__ C)
{
    extern __shared__ __nv_bfloat16 gs[];
    __nv_bfloat16* Ahs = gs;
    __nv_bfloat16* Als = Ahs + 128 * GTS;
    __nv_bfloat16* Bhs = Als + 128 * GTS;
    __nv_bfloat16* Bls = Bhs + 128 * GTS;

    int tid = threadIdx.x;
    int lane = tid & 31, wrp = tid >> 5;
    int wm = wrp & 1, wn = wrp >> 1;
    int gr = lane >> 2, tig = lane & 3;
    int m0 = blockIdx.x * 128;
    int n0 = blockIdx.y * 128;

    const __nv_bfloat16* Ahg = g_hidh + (size_t)m0 * Hdim;
    const __nv_bfloat16* Alg = g_hidl + (size_t)m0 * Hdim;
    const __nv_bfloat16* Bhg = g_embh + (size_t)n0 * Hdim;
    const __nv_bfloat16* Blg = g_embl + (size_t)n0 * Hdim;

    float acc[4][4][4];
#pragma unroll
    for (int i = 0; i < 4; i++)
#pragma unroll
        for (int j = 0; j < 4; j++)
#pragma unroll
            for (int q = 0; q < 4; q++) acc[i][j][q] = 0.f;

    for (int kc = 0; kc < Hdim; kc += 64) {
        __syncthreads();
#pragma unroll
        for (int i = 0; i < 4; i++) {
            int idx = tid + i * 256;
            int r = idx >> 3, u = idx & 7;
            int so = r * GTS + u * 8;
            size_t go = (size_t)r * Hdim + kc + u * 8;
            *(uint4*)&Ahs[so] = *(const uint4*)&Ahg[go];
            *(uint4*)&Als[so] = *(const uint4*)&Alg[go];
            *(uint4*)&Bhs[so] = *(const uint4*)&Bhg[go];
            *(uint4*)&Bls[so] = *(const uint4*)&Blg[go];
        }
        __syncthreads();

#pragma unroll
        for (int ks = 0; ks < 4; ks++) {
            int kb = ks * 16;
            uint32_t ah[4][4], al[4][4], bh[4][2], bl[4][2];
#pragma unroll
            for (int mf = 0; mf < 4; mf++) {
                int base = (wm * 64 + mf * 16 + gr) * GTS + kb + 2 * tig;
                ah[mf][0] = *(const uint32_t*)&Ahs[base];
                ah[mf][1] = *(const uint32_t*)&Ahs[base + 8 * GTS];
                ah[mf][2] = *(const uint32_t*)&Ahs[base + 8];
                ah[mf][3] = *(const uint32_t*)&Ahs[base + 8 * GTS + 8];
                al[mf][0] = *(const uint32_t*)&Als[base];
                al[mf][1] = *(const uint32_t*)&Als[base + 8 * GTS];
                al[mf][2] = *(const uint32_t*)&Als[base + 8];
                al[mf][3] = *(const uint32_t*)&Als[base + 8 * GTS + 8];
            }
#pragma unroll
            for (int nf = 0; nf < 4; nf++) {
                int base = (wn * 32 + nf * 8 + gr) * GTS + kb + 2 * tig;
                bh[nf][0] = *(const uint32_t*)&Bhs[base];
                bh[nf][1] = *(const uint32_t*)&Bhs[base + 8];
                bl[nf][0] = *(const uint32_t*)&Bls[base];
                bl[nf][1] = *(const uint32_t*)&Bls[base + 8];
            }
#pragma unroll
            for (int mf = 0; mf < 4; mf++)
#pragma unroll
                for (int nf = 0; nf < 4; nf++) {
                    mma_bf16(acc[mf][nf], ah[mf], bh[nf]);
                    mma_bf16(acc[mf][nf], al[mf], bh[nf]);
                    mma_bf16(acc[mf][nf], ah[mf], bl[nf]);
                }
        }
    }

#pragma unroll
    for (int nf = 0; nf < 4; nf++) {
        int col = n0 + wn * 32 + nf * 8 + 2 * tig;
        float bv0 = bias[col], bv1 = bias[col + 1];
#pragma unroll
        for (int mf = 0; mf < 4; mf++) {
            int row = m0 + wm * 64 + mf * 16 + gr;
            float2 v0 = make_float2(acc[mf][nf][0] + bv0, acc[mf][nf][1] + bv1);
            float2 v1 = make_float2(acc[mf][nf][2] + bv0, acc[mf][nf][3] + bv1);
            *(float2*)&C[(size_t)row * Vsz + col] = v0;
            *(float2*)&C[(size_t)(row + 8) * Vsz + col] = v1;
        }
    }
}

// ---------------- host ----------------
extern "C" void kernel_launch(void* const* d_in, const int* in_sizes, int n_in,
                              void* d_out, int out_size) {
    (void)in_sizes; (void)out_size;
    const int* seq = (const int*)d_in[0];
    int o = n_in - 14;
    const float* emb  = (const float*)d_in[o + 0];
    const float* fc_b = (const float*)d_in[o + 1];
    const float* m1w  = (const float*)d_in[o + 2];
    const float* m1b  = (const float*)d_in[o + 3];
    const float* w1ih = (const float*)d_in[o + 4];
    const float* w1hh = (const float*)d_in[o + 5];
    const float* b1ih = (const float*)d_in[o + 6];
    const float* b1hh = (const float*)d_in[o + 7];
    const float* m2w  = (const float*)d_in[o + 8];
    const float* m2b  = (const float*)d_in[o + 9];
    const float* w2ih = (const float*)d_in[o + 10];
    const float* w2hh = (const float*)d_in[o + 11];
    const float* b2ih = (const float*)d_in[o + 12];
    const float* b2hh = (const float*)d_in[o + 13];

    float* outp = (float*)d_out;                          // [B][T][V]
    float* hidp = outp + (size_t)Bsz * Tlen * Vsz;        // [B][T][H]

    __nv_bfloat16 *embh, *embl, *hidh, *hidl, *wh, *wl;
    cudaGetSymbolAddress((void**)&embh, g_embh);
    cudaGetSymbolAddress((void**)&embl, g_embl);
    cudaGetSymbolAddress((void**)&hidh, g_hidh);
    cudaGetSymbolAddress((void**)&hidl, g_hidl);
    cudaGetSymbolAddress((void**)&wh, g_wh);
    cudaGetSymbolAddress((void**)&wl, g_wl);

    cudaFuncSetAttribute(mog_lstm_kernel,
                         cudaFuncAttributeMaxDynamicSharedMemorySize, R_SMEM_BYTES);
    cudaFuncSetAttribute(gemm_bf16x3_bias,
                         cudaFuncAttributeMaxDynamicSharedMemorySize, G_SMEM_BYTES);

    // split weights into bf16 hi/lo arena
    split_bf16_kernel<<<512, 256>>>(m1w,  wh + WOFF_M1,   wl + WOFF_M1,   (size_t)5 * Hdim * Hdim / 4);
    split_bf16_kernel<<<512, 256>>>(m2w,  wh + WOFF_M2,   wl + WOFF_M2,   (size_t)5 * Hdim * Hdim / 4);
    split_bf16_kernel<<<512, 256>>>(w1ih, wh + WOFF_G1IH, wl + WOFF_G1IH, (size_t)4 * Hdim * Hdim / 4);
    split_bf16_kernel<<<512, 256>>>(w1hh, wh + WOFF_G1HH, wl + WOFF_G1HH, (size_t)4 * Hdim * Hdim / 4);
    split_bf16_kernel<<<512, 256>>>(w2ih, wh + WOFF_G2IH, wl + WOFF_G2IH, (size_t)4 * Hdim * Hdim / 4);
    split_bf16_kernel<<<512, 256>>>(w2hh, wh + WOFF_G2HH, wl + WOFF_G2HH, (size_t)4 * Hdim * Hdim / 4);

    // split embedding (independent of recurrence result)
    split_bf16_kernel<<<2048, 256>>>(emb, embh, embl, (size_t)Vsz * Hdim / 4);

    mog_lstm_kernel<<<NB, NT, R_SMEM_BYTES>>>(seq, emb,
                                              m1b, b1ih, b1hh, m2b, b2ih, b2hh, hidp);

    // split hidden states produced by the recurrence
    split_bf16_kernel<<<1024, 256>>>(hidp, hidh, hidl, (size_t)Bsz * Tlen * Hdim / 4);

    gemm_bf16x3_bias<<<dim3((Bsz * Tlen) / 128, Vsz / 128), 256, G_SMEM_BYTES>>>(fc_b, outp);
}

// round 15
// speedup vs baseline: 1.0266x; 1.0266x over previous
#include <cuda_runtime.h>
#include <cuda_bf16.h>
#include <math.h>
#include <stdint.h>

#define Bsz 32
#define Tlen 128
#define Hdim 1024
#define Vsz 32000
#define NB 128
#define NBG 64
#define NT 512

// ---------------- recurrence smem layout (byte offsets) ----------------
#define RTS1  264
#define RTS1B 528
#define RTS2  136
#define RTS2B 272
#define WSLOT 34816
#define SW_H(b) ((b) * WSLOT)
#define SW_L(b) ((b) * WSLOT + 17408)
#define SX_H(b) (139264 + (b) * 33792)
#define SX_L(b) (139264 + (b) * 33792 + 16896)
// P overlays W buffer 0 (written only after all W reads complete, sync-separated)
#define SP_OFF  0
#define R_SMEM_BYTES 206848

// ---------------- device scratch ----------------
__device__ float g_XT[Tlen * Bsz * Hdim];        // [t][b][k]
__device__ float g_h1a[Bsz * Hdim], g_h1b[Bsz * Hdim];
__device__ float g_h2a[Bsz * Hdim], g_h2b[Bsz * Hdim];
__device__ float g_c1[Bsz * Hdim],  g_c2[Bsz * Hdim];
__device__ float g_xA1[Bsz * Hdim], g_xB1[Bsz * Hdim];
__device__ float g_hA1[Bsz * Hdim], g_hB1[Bsz * Hdim];
__device__ float g_xA2[Bsz * Hdim], g_xB2[Bsz * Hdim];
__device__ float g_hA2[Bsz * Hdim], g_hB2[Bsz * Hdim];
__device__ unsigned g_gcount;
__device__ volatile unsigned g_gsense;
__device__ unsigned g_lcount[2];
__device__ volatile unsigned g_lsense[2];

// bf16 hi/lo weight arena
#define WOFF_M1   0
#define WOFF_M2   5242880
#define WOFF_G1IH 10485760
#define WOFF_G1HH 14680064
#define WOFF_G2IH 18874368
#define WOFF_G2HH 23068672
#define WTOTAL    27262976
__device__ __nv_bfloat16 g_wh[WTOTAL];
__device__ __nv_bfloat16 g_wl[WTOTAL];

// bf16 hi/lo splits for logits GEMM
__device__ __nv_bfloat16 g_embh[(size_t)Vsz * Hdim];
__device__ __nv_bfloat16 g_embl[(size_t)Vsz * Hdim];
__device__ __nv_bfloat16 g_hidh[(size_t)Bsz * Tlen * Hdim];
__device__ __nv_bfloat16 g_hidl[(size_t)Bsz * Tlen * Hdim];

// ---------------- barriers (sense reversing, replay-safe) ----------------
__device__ __forceinline__ void global_barrier(unsigned& sense) {
    __threadfence();
    __syncthreads();
    if (threadIdx.x == 0) {
        unsigned s = sense ^ 1u;
        if (atomicAdd(&g_gcount, 1u) == NB - 1u) {
            g_gcount = 0u;
            __threadfence();
            g_gsense = s;
        } else {
            while (g_gsense != s) __nanosleep(32);
        }
    }
    __syncthreads();
    __threadfence();
    sense ^= 1u;
}

__device__ __forceinline__ void group_barrier(int grp, unsigned& sense) {
    __threadfence();
    __syncthreads();
    if (threadIdx.x == 0) {
        unsigned s = sense ^ 1u;
        if (atomicAdd(&g_lcount[grp], 1u) == NBG - 1u) {
            g_lcount[grp] = 0u;
            __threadfence();
            g_lsense[grp] = s;
        } else {
            while (g_lsense[grp] != s) __nanosleep(32);
        }
    }
    __syncthreads();
    __threadfence();
    sense ^= 1u;
}

// ---------------- helpers ----------------
__device__ __forceinline__ void mma_bf16(float d[4], const uint32_t a[4],
                                         const uint32_t b[2]) {
    asm volatile(
        "mma.sync.aligned.m16n8k16.row.col.f32.bf16.bf16.f32 "
        "{%0,%1,%2,%3},{%4,%5,%6,%7},{%8,%9},{%0,%1,%2,%3};"
        : "+f"(d[0]), "+f"(d[1]), "+f"(d[2]), "+f"(d[3])
        : "r"(a[0]), "r"(a[1]), "r"(a[2]), "r"(a[3]), "r"(b[0]), "r"(b[1]));
}

__device__ __forceinline__ void cp16(uint32_t saddr, const void* g) {
    asm volatile("cp.async.cg.shared.global [%0], [%1], 16;" :: "r"(saddr), "l"(g));
}
#define CP_COMMIT() asm volatile("cp.async.commit_group;" ::: "memory")
template <int N>
__device__ __forceinline__ void cp_wait() {
    asm volatile("cp.async.wait_group %0;" :: "n"(N) : "memory");
}

__device__ __forceinline__ uint32_t pack_bf2(float a, float b) {
    __nv_bfloat162 t(__float2bfloat16_rn(a), __float2bfloat16_rn(b));
    return *(uint32_t*)&t;
}

// ---- activation staging ----
template <int KCH, int RTSBx>
__device__ __forceinline__ void x_prefetch(const float* __restrict__ src, int kb,
                                           float4* xr) {
    int tid = threadIdx.x;
    const int CELLS = Bsz * KCH / 4;
#pragma unroll
    for (int i = 0; i < CELLS / NT; i++) {
        int idx = tid + i * NT;
        int b = idx / (KCH / 4), q = idx % (KCH / 4);
        xr[i] = *(const float4*)&src[(size_t)b * Hdim + kb + q * 4];
    }
}
template <int KCH, int RTSBx>
__device__ __forceinline__ void x_store(char* sm, int buf, const float4* xr) {
    int tid = threadIdx.x;
    char* XH = sm + SX_H(buf);
    char* XL = sm + SX_L(buf);
    const int CELLS = Bsz * KCH / 4;
#pragma unroll
    for (int i = 0; i < CELLS / NT; i++) {
        int idx = tid + i * NT;
        int b = idx / (KCH / 4), q = idx % (KCH / 4);
        float4 v = xr[i];
        float hx = __bfloat162float(__float2bfloat16_rn(v.x));
        float hy = __bfloat162float(__float2bfloat16_rn(v.y));
        float hz = __bfloat162float(__float2bfloat16_rn(v.z));
        float hw = __bfloat162float(__float2bfloat16_rn(v.w));
        uint2 uh = make_uint2(pack_bf2(v.x, v.y), pack_bf2(v.z, v.w));
        uint2 ul = make_uint2(pack_bf2(v.x - hx, v.y - hy), pack_bf2(v.z - hz, v.w - hw));
        int off = b * RTSBx + q * 8;
        *(uint2*)(XH + off) = uh;
        *(uint2*)(XL + off) = ul;
    }
}

// ---- m16 fragment mma ----
template <int RTSx, int KSTEPS>
__device__ __forceinline__ void frag16(char* sm, int wbuf, int xbuf, int rowBase,
                                       int kw, int gr, int tig, float acc[4][4]) {
    const __nv_bfloat16* WhS = (const __nv_bfloat16*)(sm + SW_H(wbuf));
    const __nv_bfloat16* WlS = (const __nv_bfloat16*)(sm + SW_L(wbuf));
    const __nv_bfloat16* XhS = (const __nv_bfloat16*)(sm + SX_H(xbuf));
    const __nv_bfloat16* XlS = (const __nv_bfloat16*)(sm + SX_L(xbuf));
#pragma unroll
    for (int ks = 0; ks < KSTEPS; ks++) {
        int k0 = kw + ks * 16 + 2 * tig;
        uint32_t ah[4], al[4], bh[4][2], bl[4][2];
        int base = (rowBase + gr) * RTSx + k0;
        ah[0] = *(const uint32_t*)&WhS[base];
        ah[1] = *(const uint32_t*)&WhS[base + 8 * RTSx];
        ah[2] = *(const uint32_t*)&WhS[base + 8];
        ah[3] = *(const uint32_t*)&WhS[base + 8 * RTSx + 8];
        al[0] = *(const uint32_t*)&WlS[base];
        al[1] = *(const uint32_t*)&WlS[base + 8 * RTSx];
        al[2] = *(const uint32_t*)&WlS[base + 8];
        al[3] = *(const uint32_t*)&WlS[base + 8 * RTSx + 8];
#pragma unroll
        for (int nf = 0; nf < 4; nf++) {
            int xb = (nf * 8 + gr) * RTSx + k0;
            bh[nf][0] = *(const uint32_t*)&XhS[xb];
            bh[nf][1] = *(const uint32_t*)&XhS[xb + 8];
            bl[nf][0] = *(const uint32_t*)&XlS[xb];
            bl[nf][1] = *(const uint32_t*)&XlS[xb + 8];
        }
#pragma unroll
        for (int nf = 0; nf < 4; nf++) {
            mma_bf16(acc[nf], ah, bh[nf]);
            mma_bf16(acc[nf], al, bh[nf]);
            mma_bf16(acc[nf], ah, bl[nf]);
        }
    }
}

// ---------------- mogrify stage: 16 rows/block, full K, 4 chunks in flight ----------
__device__ void mog_stage(const __nv_bfloat16* __restrict__ Wh,
                          const __nv_bfloat16* __restrict__ Wl,
                          const float* __restrict__ bias,
                          const float* __restrict__ src,
                          const float* __restrict__ mult,
                          float* __restrict__ dstNew,
                          int lb, char* sm, uint32_t smb)
{
    int tid = threadIdx.x, lane = tid & 31, w = tid >> 5;
    int gr = lane >> 2, tig = lane & 3;
    int j0 = lb * 16;
    float* P = (float*)(sm + SP_OFF);

    float acc[4][4];
#pragma unroll
    for (int nf = 0; nf < 4; nf++)
#pragma unroll
        for (int q = 0; q < 4; q++) acc[nf][q] = 0.f;

    int wr = tid >> 5, wu = tid & 31;
    size_t wgbase = (size_t)(j0 + wr) * Hdim + wu * 8;
    uint32_t wsoff = wr * RTS1B + wu * 16;

#pragma unroll
    for (int c = 0; c < 4; c++) {
        cp16(smb + SW_H(c) + wsoff, Wh + wgbase + c * 256);
        cp16(smb + SW_L(c) + wsoff, Wl + wgbase + c * 256);
        CP_COMMIT();
    }
    {
        float4 xr[4];
        x_prefetch<256, RTS1B>(src, 0, xr);
        x_store<256, RTS1B>(sm, 0, xr);
    }

#pragma unroll
    for (int c = 0; c < 4; c++) {
        float4 xr[4];
        if (c < 3) x_prefetch<256, RTS1B>(src, (c + 1) * 256, xr);
        if (c == 0) cp_wait<3>();
        else if (c == 1) cp_wait<2>();
        else if (c == 2) cp_wait<1>();
        else cp_wait<0>();
        __syncthreads();
        frag16<RTS1, 1>(sm, c, c & 1, 0, w * 16, gr, tig, acc);
        if (c < 3) x_store<256, RTS1B>(sm, (c + 1) & 1, xr);
        __syncthreads();
    }

#pragma unroll
    for (int nf = 0; nf < 4; nf++) {
        int cc = nf * 8 + 2 * tig;
        *(float2*)&P[w * 512 + gr * 32 + cc]       = make_float2(acc[nf][0], acc[nf][1]);
        *(float2*)&P[w * 512 + (gr + 8) * 32 + cc] = make_float2(acc[nf][2], acc[nf][3]);
    }
    __syncthreads();

    {
        float s = 0.f;
#pragma unroll
        for (int ww = 0; ww < 16; ww++) s += P[ww * 512 + tid];
        int row = tid >> 5, b = tid & 31;
        int j = j0 + row;
        s += bias[j];
        size_t o = (size_t)b * Hdim + j;
        dstNew[o] = mult[o] * (2.f / (1.f + __expf(-s)));
    }
}

// ---------------- gate stage: 64 rows/block, K=2048, 128k chunks, 3-ahead ----------
__device__ void gate_stage(const __nv_bfloat16* __restrict__ WihH,
                           const __nv_bfloat16* __restrict__ WihL,
                           const __nv_bfloat16* __restrict__ WhhH,
                           const __nv_bfloat16* __restrict__ WhhL,
                           const float* __restrict__ bih, const float* __restrict__ bhh,
                           const float* __restrict__ xsrc, const float* __restrict__ hsrc,
                           float* __restrict__ cSt, float* __restrict__ hDst,
                           float* __restrict__ hidOut, int t,
                           int lb, char* sm, uint32_t smb)
{
    int tid = threadIdx.x, lane = tid & 31, w = tid >> 5;
    int gr = lane >> 2, tig = lane & 3;
    int mg = w >> 2, kg = w & 3;
    int j0u = lb * 16;
    float* P = (float*)(sm + SP_OFF);

    float acc[4][4];
#pragma unroll
    for (int nf = 0; nf < 4; nf++)
#pragma unroll
        for (int q = 0; q < 4; q++) acc[nf][q] = 0.f;

    auto stageW = [&](int buf, int cn) {
        const __nv_bfloat16* WmH = (cn < 8) ? WihH : WhhH;
        const __nv_bfloat16* WmL = (cn < 8) ? WihL : WhhL;
        int cbase = (cn & 7) * 128;
#pragma unroll
        for (int i = 0; i < 2; i++) {
            int idx = tid + i * NT;
            int r = idx >> 4, u = idx & 15;
            int grow = (r >> 4) * Hdim + j0u + (r & 15);
            size_t go = (size_t)grow * Hdim + cbase + u * 8;
            cp16(smb + SW_H(buf) + r * RTS2B + u * 16, WmH + go);
            cp16(smb + SW_L(buf) + r * RTS2B + u * 16, WmL + go);
        }
        CP_COMMIT();
    };

    stageW(0, 0);
    stageW(1, 1);
    stageW(2, 2);
    {
        float4 xr[2];
        x_prefetch<128, RTS2B>(xsrc, 0, xr);
        x_store<128, RTS2B>(sm, 0, xr);
    }

#pragma unroll
    for (int c = 0; c < 16; c++) {
        if (c + 3 < 16) stageW((c + 3) & 3, c + 3);
        float4 xr[2];
        if (c < 15) {
            int cn = c + 1;
            const float* S = (cn < 8) ? xsrc : hsrc;
            x_prefetch<128, RTS2B>(S, (cn & 7) * 128, xr);
        }
        if (c <= 12) cp_wait<3>();
        else if (c == 13) cp_wait<2>();
        else if (c == 14) cp_wait<1>();
        else cp_wait<0>();
        __syncthreads();
        frag16<RTS2, 2>(sm, c & 3, c & 1, mg * 16, kg * 32, gr, tig, acc);
        if (c < 15) x_store<128, RTS2B>(sm, (c + 1) & 1, xr);
        __syncthreads();
    }

#pragma unroll
    for (int nf = 0; nf < 4; nf++) {
        int cc = nf * 8 + 2 * tig;
        *(float2*)&P[kg * 2048 + (mg * 16 + gr) * 32 + cc] =
            make_float2(acc[nf][0], acc[nf][1]);
        *(float2*)&P[kg * 2048 + (mg * 16 + gr + 8) * 32 + cc] =
            make_float2(acc[nf][2], acc[nf][3]);
    }
    __syncthreads();

    {
        int u = tid >> 5, b = tid & 31;
        int j = j0u + u;
        float s[4];
#pragma unroll
        for (int g = 0; g < 4; g++) {
            int row = g * 16 + u;
            float v = 0.f;
#pragma unroll
            for (int k = 0; k < 4; k++) v += P[k * 2048 + row * 32 + b];
            s[g] = v;
        }
        float gi = s[0] + bih[j]            + bhh[j];
        float gf = s[1] + bih[Hdim + j]     + bhh[Hdim + j];
        float gg = s[2] + bih[2 * Hdim + j] + bhh[2 * Hdim + j];
        float go = s[3] + bih[3 * Hdim + j] + bhh[3 * Hdim + j];

        float si = 1.f / (1.f + __expf(-gi));
        float sf = 1.f / (1.f + __expf(-gf));
        float tg = tanhf(gg);
        float so = 1.f / (1.f + __expf(-go));

        size_t g = (size_t)b * Hdim + j;
        float cc = sf * cSt[g] + si * tg;
        float h = so * tanhf(cc);
        cSt[g] = cc;
        hDst[g] = h;
        if (hidOut) hidOut[(size_t)b * Tlen * Hdim + (size_t)t * Hdim + j] = h;
    }
}

// ---------------- persistent recurrence kernel (two-level barriers) ----------------
__global__ __launch_bounds__(NT, 1) void mog_lstm_kernel(
    const int* __restrict__ seq, const float* __restrict__ emb,
    const float* __restrict__ m1b, const float* __restrict__ b1ih,
    const float* __restrict__ b1hh, const float* __restrict__ m2b,
    const float* __restrict__ b2ih, const float* __restrict__ b2hh,
    float* __restrict__ hidp)
{
    extern __shared__ char sm[];
    uint32_t smb;
    asm("{ .reg .u64 t; cvta.to.shared.u64 t, %1; cvt.u32.u64 %0, t; }"
        : "=r"(smb) : "l"(sm));
    int tid = threadIdx.x;
    int bid = blockIdx.x;
    int grp = bid >> 6;
    int lb  = bid & 63;
    unsigned gsn = 0, lsn = 0;

    for (int g = bid * NT + tid; g < Bsz * Hdim; g += NB * NT) {
        g_h1a[g] = 0.f; g_h1b[g] = 0.f; g_h2a[g] = 0.f; g_h2b[g] = 0.f;
        g_c1[g] = 0.f;  g_c2[g] = 0.f;
    }
    {
        int t = bid;
        for (int idx = tid; idx < Bsz * Hdim; idx += NT) {
            int b = idx >> 10, k = idx & 1023;
            int id = seq[b * Tlen + t];
            g_XT[((size_t)t * Bsz + b) * Hdim + k] = emb[(size_t)id * Hdim + k];
        }
    }
    global_barrier(gsn);                                    // global #1

    const size_t MW = (size_t)Hdim * Hdim;
    for (int p = 0; p <= Tlen; p++) {
        bool Aact = (grp == 0) && (p < Tlen);
        bool Bact = (grp == 1) && (p >= 1);
        int t2 = p - 1;

        const float* A_x = g_XT + (size_t)p * Bsz * Hdim;
        float* A_hs = (p & 1) ? g_h1b : g_h1a;
        float* A_hd = (p & 1) ? g_h1a : g_h1b;
        const float* B_x = (t2 & 1) ? g_h1a : g_h1b;
        float* B_hs = (t2 & 1) ? g_h2b : g_h2a;
        float* B_hd = (t2 & 1) ? g_h2a : g_h2b;

        const float* AsS[5] = { A_hs, g_xA1, g_hA1, g_xB1, g_hB1 };
        const float* AsM[5] = { A_x,  A_hs,  g_xA1, g_hA1, g_xB1 };
        float*       AsD[5] = { g_xA1, g_hA1, g_xB1, g_hB1, g_xA1 };
        const float* BsS[5] = { B_hs, g_xA2, g_hA2, g_xB2, g_hB2 };
        const float* BsM[5] = { B_x,  B_hs,  g_xA2, g_hA2, g_xB2 };
        float*       BsD[5] = { g_xA2, g_hA2, g_xB2, g_hB2, g_xA2 };

        for (int i = 0; i < 5; i++) {
            if (Aact)
                mog_stage(g_wh + WOFF_M1 + (size_t)i * MW, g_wl + WOFF_M1 + (size_t)i * MW,
                          m1b + i * Hdim, AsS[i], AsM[i], AsD[i], lb, sm, smb);
            else if (Bact)
                mog_stage(g_wh + WOFF_M2 + (size_t)i * MW, g_wl + WOFF_M2 + (size_t)i * MW,
                          m2b + i * Hdim, BsS[i], BsM[i], BsD[i], lb, sm, smb);
            group_barrier(grp, lsn);                        // 5 per phase, group-local
        }
        if (Aact)
            gate_stage(g_wh + WOFF_G1IH, g_wl + WOFF_G1IH,
                       g_wh + WOFF_G1HH, g_wl + WOFF_G1HH,
                       b1ih, b1hh, g_xA1, g_hB1, g_c1, A_hd, nullptr, p, lb, sm, smb);
        else if (Bact)
            gate_stage(g_wh + WOFF_G2IH, g_wl + WOFF_G2IH,
                       g_wh + WOFF_G2HH, g_wl + WOFF_G2HH,
                       b2ih, b2hh, g_xA2, g_hB2, g_c2, B_hd, hidp, t2, lb, sm, smb);
        global_barrier(gsn);                                // 1 per phase
    }
    group_barrier(grp, lsn);   // pad: group flips = 129*5+1 = 646 (even)
    // global flips = 1 + 129 = 130 (even) -> all sense words restored for replay
}

// ================= bf16 hi/lo split =================
__global__ void split_bf16_kernel(const float* __restrict__ src,
                                  __nv_bfloat16* __restrict__ hi,
                                  __nv_bfloat16* __restrict__ lo, size_t n4)
{
    for (size_t i = blockIdx.x * blockDim.x + threadIdx.x; i < n4;
         i += (size_t)gridDim.x * blockDim.x) {
        float4 v = *(const float4*)(src + i * 4);
        __nv_bfloat16 h0 = __float2bfloat16_rn(v.x);
        __nv_bfloat16 h1 = __float2bfloat16_rn(v.y);
        __nv_bfloat16 h2 = __float2bfloat16_rn(v.z);
        __nv_bfloat16 h3 = __float2bfloat16_rn(v.w);
        __nv_bfloat16 l0 = __float2bfloat16_rn(v.x - __bfloat162float(h0));
        __nv_bfloat16 l1 = __float2bfloat16_rn(v.y - __bfloat162float(h1));
        __nv_bfloat16 l2 = __float2bfloat16_rn(v.z - __bfloat162float(h2));
        __nv_bfloat16 l3 = __float2bfloat16_rn(v.w - __bfloat162float(h3));
        __nv_bfloat162* hp = (__nv_bfloat162*)(hi + i * 4);
        __nv_bfloat162* lp = (__nv_bfloat162*)(lo + i * 4);
        hp[0] = __nv_bfloat162(h0, h1);
        hp[1] = __nv_bfloat162(h2, h3);
        lp[0] = __nv_bfloat162(l0, l1);
        lp[1] = __nv_bfloat162(l2, l3);
    }
}

// ================= bf16x3 legacy-mma logits GEMM (unchanged, passing) =================
#define GTS 72
#define G_SMEM_BYTES (4 * 128 * GTS * 2)

__global__ __launch_bounds__(256, 2) void gemm_bf16x3_bias(
    const float* __restrict__ bias, float* __restrict__ C)
{
    extern __shared__ __nv_bfloat16 gs[];
    __nv_bfloat16* Ahs = gs;
    __nv_bfloat16* Als = Ahs + 128 * GTS;
    __nv_bfloat16* Bhs = Als + 128 * GTS;
    __nv_bfloat16* Bls = Bhs + 128 * GTS;

    int tid = threadIdx.x;
    int lane = tid & 31, wrp = tid >> 5;
    int wm = wrp & 1, wn = wrp >> 1;
    int gr = lane >> 2, tig = lane & 3;
    int m0 = blockIdx.x * 128;
    int n0 = blockIdx.y * 128;

    const __nv_bfloat16* Ahg = g_hidh + (size_t)m0 * Hdim;
    const __nv_bfloat16* Alg = g_hidl + (size_t)m0 * Hdim;
    const __nv_bfloat16* Bhg = g_embh + (size_t)n0 * Hdim;
    const __nv_bfloat16* Blg = g_embl + (size_t)n0 * Hdim;

    float acc[4][4][4];
#pragma unroll
    for (int i = 0; i < 4; i++)
#pragma unroll
        for (int j = 0; j < 4; j++)
#pragma unroll
            for (int q = 0; q < 4; q++) acc[i][j][q] = 0.f;

    for (int kc = 0; kc < Hdim; kc += 64) {
        __syncthreads();
#pragma unroll
        for (int i = 0; i < 4; i++) {
            int idx = tid + i * 256;
            int r = idx >> 3, u = idx & 7;
            int so = r * GTS + u * 8;
            size_t go = (size_t)r * Hdim + kc + u * 8;
            *(uint4*)&Ahs[so] = *(const uint4*)&Ahg[go];
            *(uint4*)&Als[so] = *(const uint4*)&Alg[go];
            *(uint4*)&Bhs[so] = *(const uint4*)&Bhg[go];
            *(uint4*)&Bls[so] = *(const uint4*)&Blg[go];
        }
        __syncthreads();

#pragma unroll
        for (int ks = 0; ks < 4; ks++) {
            int kb = ks * 16;
            uint32_t ah[4][4], al[4][4], bh[4][2], bl[4][2];
#pragma unroll
            for (int mf = 0; mf < 4; mf++) {
                int base = (wm * 64 + mf * 16 + gr) * GTS + kb + 2 * tig;
                ah[mf][0] = *(const uint32_t*)&Ahs[base];
                ah[mf][1] = *(const uint32_t*)&Ahs[base + 8 * GTS];
                ah[mf][2] = *(const uint32_t*)&Ahs[base + 8];
                ah[mf][3] = *(const uint32_t*)&Ahs[base + 8 * GTS + 8];
                al[mf][0] = *(const uint32_t*)&Als[base];
                al[mf][1] = *(const uint32_t*)&Als[base + 8 * GTS];
                al[mf][2] = *(const uint32_t*)&Als[base + 8];
                al[mf][3] = *(const uint32_t*)&Als[base + 8 * GTS + 8];
            }
#pragma unroll
            for (int nf = 0; nf < 4; nf++) {
                int base = (wn * 32 + nf * 8 + gr) * GTS + kb + 2 * tig;
                bh[nf][0] = *(const uint32_t*)&Bhs[base];
                bh[nf][1] = *(const uint32_t*)&Bhs[base + 8];
                bl[nf][0] = *(const uint32_t*)&Bls[base];
                bl[nf][1] = *(const uint32_t*)&Bls[base + 8];
            }
#pragma unroll
            for (int mf = 0; mf < 4; mf++)
#pragma unroll
                for (int nf = 0; nf < 4; nf++) {
                    mma_bf16(acc[mf][nf], ah[mf], bh[nf]);
                    mma_bf16(acc[mf][nf], al[mf], bh[nf]);
                    mma_bf16(acc[mf][nf], ah[mf], bl[nf]);
                }
        }
    }

#pragma unroll
    for (int nf = 0; nf < 4; nf++) {
        int col = n0 + wn * 32 + nf * 8 + 2 * tig;
        float bv0 = bias[col], bv1 = bias[col + 1];
#pragma unroll
        for (int mf = 0; mf < 4; mf++) {
            int row = m0 + wm * 64 + mf * 16 + gr;
            float2 v0 = make_float2(acc[mf][nf][0] + bv0, acc[mf][nf][1] + bv1);
            float2 v1 = make_float2(acc[mf][nf][2] + bv0, acc[mf][nf][3] + bv1);
            *(float2*)&C[(size_t)row * Vsz + col] = v0;
            *(float2*)&C[(size_t)(row + 8) * Vsz + col] = v1;
        }
    }
}

// ---------------- host ----------------
extern "C" void kernel_launch(void* const* d_in, const int* in_sizes, int n_in,
                              void* d_out, int out_size) {
    (void)in_sizes; (void)out_size;
    const int* seq = (const int*)d_in[0];
    int o = n_in - 14;
    const float* emb  = (const float*)d_in[o + 0];
    const float* fc_b = (const float*)d_in[o + 1];
    const float* m1w  = (const float*)d_in[o + 2];
    const float* m1b  = (const float*)d_in[o + 3];
    const float* w1ih = (const float*)d_in[o + 4];
    const float* w1hh = (const float*)d_in[o + 5];
    const float* b1ih = (const float*)d_in[o + 6];
    const float* b1hh = (const float*)d_in[o + 7];
    const float* m2w  = (const float*)d_in[o + 8];
    const float* m2b  = (const float*)d_in[o + 9];
    const float* w2ih = (const float*)d_in[o + 10];
    const float* w2hh = (const float*)d_in[o + 11];
    const float* b2ih = (const float*)d_in[o + 12];
    const float* b2hh = (const float*)d_in[o + 13];

    float* outp = (float*)d_out;                          // [B][T][V]
    float* hidp = outp + (size_t)Bsz * Tlen * Vsz;        // [B][T][H]

    __nv_bfloat16 *embh, *embl, *hidh, *hidl, *wh, *wl;
    cudaGetSymbolAddress((void**)&embh, g_embh);
    cudaGetSymbolAddress((void**)&embl, g_embl);
    cudaGetSymbolAddress((void**)&hidh, g_hidh);
    cudaGetSymbolAddress((void**)&hidl, g_hidl);
    cudaGetSymbolAddress((void**)&wh, g_wh);
    cudaGetSymbolAddress((void**)&wl, g_wl);

    cudaFuncSetAttribute(mog_lstm_kernel,
                         cudaFuncAttributeMaxDynamicSharedMemorySize, R_SMEM_BYTES);
    cudaFuncSetAttribute(gemm_bf16x3_bias,
                         cudaFuncAttributeMaxDynamicSharedMemorySize, G_SMEM_BYTES);

    // split weights into bf16 hi/lo arena
    split_bf16_kernel<<<512, 256>>>(m1w,  wh + WOFF_M1,   wl + WOFF_M1,   (size_t)5 * Hdim * Hdim / 4);
    split_bf16_kernel<<<512, 256>>>(m2w,  wh + WOFF_M2,   wl + WOFF_M2,   (size_t)5 * Hdim * Hdim / 4);
    split_bf16_kernel<<<512, 256>>>(w1ih, wh + WOFF_G1IH, wl + WOFF_G1IH, (size_t)4 * Hdim * Hdim / 4);
    split_bf16_kernel<<<512, 256>>>(w1hh, wh + WOFF_G1HH, wl + WOFF_G1HH, (size_t)4 * Hdim * Hdim / 4);
    split_bf16_kernel<<<512, 256>>>(w2ih, wh + WOFF_G2IH, wl + WOFF_G2IH, (size_t)4 * Hdim * Hdim / 4);
    split_bf16_kernel<<<512, 256>>>(w2hh, wh + WOFF_G2HH, wl + WOFF_G2HH, (size_t)4 * Hdim * Hdim / 4);

    // split embedding (independent of recurrence result)
    split_bf16_kernel<<<2048, 256>>>(emb, embh, embl, (size_t)Vsz * Hdim / 4);

    mog_lstm_kernel<<<NB, NT, R_SMEM_BYTES>>>(seq, emb,
                                              m1b, b1ih, b1hh, m2b, b2ih, b2hh, hidp);

    // split hidden states produced by the recurrence
    split_bf16_kernel<<<1024, 256>>>(hidp, hidh, hidl, (size_t)Bsz * Tlen * Hdim / 4);

    gemm_bf16x3_bias<<<dim3((Bsz * Tlen) / 128, Vsz / 128), 256, G_SMEM_BYTES>>>(fc_b, outp);
}